// round 13
// baseline (speedup 1.0000x reference)
#include <cuda_runtime.h>

#define N_NODES 50000
#define N_EDGES 800000
#define ET (N_EDGES + N_NODES)   // self-loops appended
#define N_GRAPHS 64
#define FULL 0xffffffffu
#define NB_SCAN ((N_NODES + 255) / 256)   // 196
#define L2_BLOCKS (N_NODES / 16)          // 3125 blocks, 2 dst/warp * 8 warps
#define G1_BLOCKS 782                     // (391, 2)
#define CNT_CHUNK ((ET + G1_BLOCKS - 1) / G1_BLOCKS)       // 1087
#define POOL_CHUNK ((N_NODES + G1_BLOCKS - 1) / G1_BLOCKS) // 64
#define L1_WARPS (148 * 3 * 8)            // persistent: 444 blocks x 8 warps

// ---------------- scratch (device globals; zero at module load) ------------
__device__ __align__(16) float g_xl1[N_NODES * 128];
__device__ __align__(16) float g_xr1[N_NODES * 128];
__device__ __align__(16) float g_xl2[N_NODES * 4];
__device__ __align__(16) float g_xr2[N_NODES * 4];
__device__ int g_cnt[N_NODES];          // invariant: zero at kernel_launch entry
__device__ int g_rowptr[N_NODES + 1];
__device__ int g_cursor[N_NODES];
__device__ int g_csr_src[ET];
__device__ int g_bsum[NB_SCAN];
__device__ float g_pool[N_GRAPHS * 4];  // invariant: zero at kernel_launch entry
__device__ int g_done;                  // invariant: zero at kernel_launch entry

__device__ __forceinline__ float lrelu(float v) { return v > 0.f ? v : 0.2f * v; }

// f32x2 packed FMA (sm_100+): d = a*b + d, elementwise on packed pairs
#define FMA2(d, a, b) asm("fma.rn.f32x2 %0, %1, %2, %0;" : "+l"(d) : "l"(a), "l"(b))
__device__ __forceinline__ unsigned long long pack2(float lo, float hi) {
    unsigned long long r;
    asm("mov.b64 %0, {%1, %2};" : "=l"(r) : "f"(lo), "f"(hi));
    return r;
}
__device__ __forceinline__ void unpack2(unsigned long long v, float& lo, float& hi) {
    asm("mov.b64 {%0, %1}, %2;" : "=f"(lo), "=f"(hi) : "l"(v));
}

// ---------------- GEMM1 v3 + CSR-count prologue -----------------------------
// Prologue: each of the 782 blocks counts a 1087-edge slice (atomic, LSU-bound)
// and a 64-node pool-count slice; this overlaps with other blocks' FMA phase.
#define G3_KC 32
#define G3_PAD 132
__global__ void __launch_bounds__(256, 2)
gemm1_count_kernel(const float* __restrict__ x,
                   const float* __restrict__ Wl,
                   const float* __restrict__ Wr,
                   const int* __restrict__ ei,
                   const int* __restrict__ batch) {
    int tid = threadIdx.x;
    int flat = blockIdx.y * gridDim.x + blockIdx.x;   // 0..781

    // ---- CSR count slice ----
    {
        int e0 = flat * CNT_CHUNK;
        int e1 = min(e0 + CNT_CHUNK, ET);
        for (int e = e0 + tid; e < e1; e += 256) {
            int dst = (e < N_EDGES) ? ei[N_EDGES + e] : (e - N_EDGES);
            atomicAdd(&g_cnt[dst], 1);
        }
        int n0 = flat * POOL_CHUNK;
        int n1 = min(n0 + POOL_CHUNK, N_NODES);
        for (int n = n0 + tid; n < n1; n += 256)
            atomicAdd(&g_pool[batch[n] * 4 + 3], 1.f);
    }

    // ---- GEMM tile ----
    __shared__ float xs[G3_KC][G3_PAD];
    __shared__ float ws[G3_KC][G3_PAD];
    int row0 = blockIdx.x * 128;
    const float* W = blockIdx.y ? Wr : Wl;
    int rg = tid >> 3;
    int cg = tid & 7;

    unsigned long long acc[4][8];
#pragma unroll
    for (int r = 0; r < 4; r++)
#pragma unroll
        for (int c = 0; c < 8; c++) acc[r][c] = 0ull;

    for (int k0 = 0; k0 < 128; k0 += G3_KC) {
        {
            int r = tid >> 1;
            int kb = (tid & 1) * 16;
            int grow = row0 + r;
#pragma unroll
            for (int j4 = 0; j4 < 4; j4++) {
                float4 v = make_float4(0.f, 0.f, 0.f, 0.f);
                if (grow < N_NODES)
                    v = *(const float4*)(x + (size_t)grow * 128 + k0 + kb + j4 * 4);
                xs[kb + j4 * 4 + 0][r] = v.x;
                xs[kb + j4 * 4 + 1][r] = v.y;
                xs[kb + j4 * 4 + 2][r] = v.z;
                xs[kb + j4 * 4 + 3][r] = v.w;
            }
        }
        {
            int k = tid >> 3;
            int cs = (tid & 7) * 16;
#pragma unroll
            for (int j4 = 0; j4 < 4; j4++) {
                float4 v = *(const float4*)(W + (size_t)(k0 + k) * 128 + cs + j4 * 4);
                *(float4*)&ws[k][cs + j4 * 4] = v;
            }
        }
        __syncthreads();
#pragma unroll 4
        for (int k = 0; k < G3_KC; k++) {
            float4 av = *(const float4*)&xs[k][rg * 4];
            unsigned long long ap[4];
            ap[0] = pack2(av.x, av.x);
            ap[1] = pack2(av.y, av.y);
            ap[2] = pack2(av.z, av.z);
            ap[3] = pack2(av.w, av.w);
#pragma unroll
            for (int s = 0; s < 4; s++) {
                float4 bv = *(const float4*)&ws[k][cg * 4 + s * 32];
                unsigned long long b0 = pack2(bv.x, bv.y);
                unsigned long long b1 = pack2(bv.z, bv.w);
#pragma unroll
                for (int r = 0; r < 4; r++) {
                    FMA2(acc[r][2 * s + 0], ap[r], b0);
                    FMA2(acc[r][2 * s + 1], ap[r], b1);
                }
            }
        }
        __syncthreads();
    }

    float* outbuf = blockIdx.y ? g_xr1 : g_xl1;
#pragma unroll
    for (int r = 0; r < 4; r++) {
        int grow = row0 + rg * 4 + r;
        if (grow >= N_NODES) continue;
#pragma unroll
        for (int s = 0; s < 4; s++) {
            float4 o;
            unpack2(acc[r][2 * s + 0], o.x, o.y);
            unpack2(acc[r][2 * s + 1], o.z, o.w);
            *(float4*)(outbuf + (size_t)grow * 128 + cg * 4 + s * 32) = o;
        }
    }
}

// ---------------- scan phase 1: per-block exclusive scan --------------------
__global__ void scan_local_kernel() {
    __shared__ int sh[256];
    int t = threadIdx.x;
    int i = blockIdx.x * 256 + t;
    int v = (i < N_NODES) ? g_cnt[i] : 0;
    sh[t] = v;
    __syncthreads();
#pragma unroll
    for (int off = 1; off < 256; off <<= 1) {
        int u = (t >= off) ? sh[t - off] : 0;
        __syncthreads();
        sh[t] += u;
        __syncthreads();
    }
    if (i < N_NODES) g_rowptr[i] = sh[t] - v;          // exclusive within block
    if (t == 255) g_bsum[blockIdx.x] = sh[255];        // block total
}

// ---------------- scan phase 2: apply + restore g_cnt invariant -------------
__global__ void scan_apply_kernel() {
    __shared__ int sh[256];
    int t = threadIdx.x, bid = blockIdx.x;
    sh[t] = (t < bid) ? g_bsum[t] : 0;   // NB_SCAN = 196 <= 256
    __syncthreads();
#pragma unroll
    for (int off = 128; off; off >>= 1) {
        if (t < off) sh[t] += sh[t + off];
        __syncthreads();
    }
    int boff = sh[0];
    int i = bid * 256 + t;
    if (i < N_NODES) {
        int r = g_rowptr[i] + boff;
        g_rowptr[i] = r;
        g_cursor[i] = r;
        g_cnt[i] = 0;                    // g_cnt dead after this: restore invariant
    }
    if (i == 0) g_rowptr[N_NODES] = ET;
}

// ---------------- CSR: scatter src ids into slots --------------------------
__global__ void csr_fill_kernel(const int* __restrict__ ei) {
    int e = blockIdx.x * blockDim.x + threadIdx.x;
    if (e >= ET) return;
    int src, dst;
    if (e < N_EDGES) { src = ei[e]; dst = ei[N_EDGES + e]; }
    else             { src = dst = e - N_EDGES; }
    int pos = atomicAdd(&g_cursor[dst], 1);
    g_csr_src[pos] = src;
}

// ---------------- fused layer1 + bias + ELU + GEMM2: persistent warps ------
// lanes 0-15 head0 (ch 0..63), 16-31 head1. 6 edges in flight per warp.
// Persistent: each warp strides over nodes (no wave churn).
#define L1_UN 6
__global__ void __launch_bounds__(256, 3)
fused_l1_kernel(const float* __restrict__ att1,
                const float* __restrict__ b1,
                const float* __restrict__ W2l,
                const float* __restrict__ W2r) {
    int gwarp = (blockIdx.x * blockDim.x + threadIdx.x) >> 5;
    int lane = threadIdx.x & 31;
    int c0 = lane * 4;
    float4 at = *(const float4*)(att1 + c0);
    float4 bias = *(const float4*)(b1 + c0);
    float w2l[4][3], w2r[4][3];
#pragma unroll
    for (int j = 0; j < 4; j++)
#pragma unroll
        for (int c = 0; c < 3; c++) {
            w2l[j][c] = W2l[(c0 + j) * 3 + c];
            w2r[j][c] = W2r[(c0 + j) * 3 + c];
        }

    for (int dst = gwarp; dst < N_NODES; dst += L1_WARPS) {
        float4 b = *(const float4*)(g_xr1 + (size_t)dst * 128 + c0);
        float4 acc = make_float4(0.f, 0.f, 0.f, 0.f);
        float denom = 0.f;

        int rs = g_rowptr[dst], re = g_rowptr[dst + 1];
        int i = rs;
        for (; i + L1_UN <= re; i += L1_UN) {
            int s[L1_UN];
#pragma unroll
            for (int u = 0; u < L1_UN; u++) s[u] = g_csr_src[i + u];   // uniform bcast
            float4 A[L1_UN];
#pragma unroll
            for (int u = 0; u < L1_UN; u++)
                A[u] = *(const float4*)(g_xl1 + (size_t)s[u] * 128 + c0);
            float P[L1_UN];
#pragma unroll
            for (int u = 0; u < L1_UN; u++)
                P[u] = at.x * lrelu(A[u].x + b.x) + at.y * lrelu(A[u].y + b.y)
                     + at.z * lrelu(A[u].z + b.z) + at.w * lrelu(A[u].w + b.w);
#pragma unroll
            for (int o = 8; o; o >>= 1) {   // 16-lane groups => per-head sums
#pragma unroll
                for (int u = 0; u < L1_UN; u++) P[u] += __shfl_xor_sync(FULL, P[u], o);
            }
#pragma unroll
            for (int u = 0; u < L1_UN; u++) {
                float e = __expf(P[u]);
                denom += e;
                acc.x += e * A[u].x; acc.y += e * A[u].y;
                acc.z += e * A[u].z; acc.w += e * A[u].w;
            }
        }
        for (; i < re; i++) {
            int src = g_csr_src[i];
            float4 a = *(const float4*)(g_xl1 + (size_t)src * 128 + c0);
            float p = at.x * lrelu(a.x + b.x) + at.y * lrelu(a.y + b.y)
                    + at.z * lrelu(a.z + b.z) + at.w * lrelu(a.w + b.w);
#pragma unroll
            for (int o = 8; o; o >>= 1) p += __shfl_xor_sync(FULL, p, o);
            float ea = __expf(p);
            denom += ea;
            acc.x += ea * a.x; acc.y += ea * a.y;
            acc.z += ea * a.z; acc.w += ea * a.w;
        }

        float w = __fdividef(1.f, denom + 1e-16f);
        float ov[4];
        ov[0] = acc.x * w + bias.x;
        ov[1] = acc.y * w + bias.y;
        ov[2] = acc.z * w + bias.z;
        ov[3] = acc.w * w + bias.w;
#pragma unroll
        for (int j = 0; j < 4; j++)
            ov[j] = ov[j] > 0.f ? ov[j] : (__expf(ov[j]) - 1.f);   // ELU

        float pl0 = 0.f, pl1 = 0.f, pl2 = 0.f, pr0 = 0.f, pr1 = 0.f, pr2 = 0.f;
#pragma unroll
        for (int j = 0; j < 4; j++) {
            pl0 += ov[j] * w2l[j][0];
            pl1 += ov[j] * w2l[j][1];
            pl2 += ov[j] * w2l[j][2];
            pr0 += ov[j] * w2r[j][0];
            pr1 += ov[j] * w2r[j][1];
            pr2 += ov[j] * w2r[j][2];
        }
#pragma unroll
        for (int s = 16; s; s >>= 1) {
            pl0 += __shfl_xor_sync(FULL, pl0, s);
            pl1 += __shfl_xor_sync(FULL, pl1, s);
            pl2 += __shfl_xor_sync(FULL, pl2, s);
            pr0 += __shfl_xor_sync(FULL, pr0, s);
            pr1 += __shfl_xor_sync(FULL, pr1, s);
            pr2 += __shfl_xor_sync(FULL, pr2, s);
        }
        if (lane == 0) {
            *(float4*)(g_xl2 + dst * 4) = make_float4(pl0, pl1, pl2, 0.f);
            *(float4*)(g_xr2 + dst * 4) = make_float4(pr0, pr1, pr2, 0.f);
        }
    }
}

// ---------------- fused layer2 + pool + (last block) MLP --------------------
// 2 dsts per warp: lanes 0-15 -> dst0, lanes 16-31 -> dst1.
__global__ void fused_l2_mlp_kernel(const float* __restrict__ att2,
                                    const float* __restrict__ b2,
                                    const int* __restrict__ batch,
                                    const float* __restrict__ Wr1,
                                    const float* __restrict__ br1,
                                    const float* __restrict__ Wr2,
                                    const float* __restrict__ br2,
                                    float* __restrict__ out) {
    int warp_g = (blockIdx.x * blockDim.x + threadIdx.x) >> 5;
    int lane = threadIdx.x & 31;
    int sl = lane & 15;
    int dst = warp_g * 2 + (lane >> 4);

    if (dst < N_NODES) {
        float a0 = att2[0], a1 = att2[1], a2 = att2[2];
        float4 rv = *(const float4*)(g_xr2 + dst * 4);
        float d = 0.f, m0 = 0.f, m1 = 0.f, m2 = 0.f;
        int rs = g_rowptr[dst], re = g_rowptr[dst + 1];
        for (int i = rs + sl; i < re; i += 16) {
            int src = g_csr_src[i];
            float4 sv = *(const float4*)(g_xl2 + src * 4);
            float p = a0 * lrelu(sv.x + rv.x) + a1 * lrelu(sv.y + rv.y)
                    + a2 * lrelu(sv.z + rv.z);
            float ea = __expf(p);
            d += ea; m0 += ea * sv.x; m1 += ea * sv.y; m2 += ea * sv.z;
        }
#pragma unroll
        for (int o = 8; o; o >>= 1) {   // reduce within 16-lane group
            d  += __shfl_xor_sync(FULL, d, o);
            m0 += __shfl_xor_sync(FULL, m0, o);
            m1 += __shfl_xor_sync(FULL, m1, o);
            m2 += __shfl_xor_sync(FULL, m2, o);
        }
        if (sl == 0) {
            float w = __fdividef(1.f, d + 1e-16f);
            int g = batch[dst];
            atomicAdd(&g_pool[g * 4 + 0], m0 * w + b2[0]);
            atomicAdd(&g_pool[g * 4 + 1], m1 * w + b2[1]);
            atomicAdd(&g_pool[g * 4 + 2], m2 * w + b2[2]);
        }
    }

    // ---- last-block ticket: the final block to finish runs the MLP ----
    __syncthreads();
    __shared__ int s_last;
    if (threadIdx.x == 0) {
        __threadfence();
        int ticket = atomicAdd(&g_done, 1);
        s_last = (ticket == gridDim.x - 1) ? 1 : 0;
    }
    __syncthreads();
    if (!s_last) return;
    __threadfence();   // acquire: all pool atomics now visible

    int g = threadIdx.x;
    if (g < N_GRAPHS) {
        float cnt = g_pool[g * 4 + 3];
        float inv = 1.f / fmaxf(cnt, 1.f);
        float v0 = g_pool[g * 4 + 0] * inv;
        float v1 = g_pool[g * 4 + 1] * inv;
        float v2 = g_pool[g * 4 + 2] * inv;
        float o0 = br2[0], o1 = br2[1], o2 = br2[2];
#pragma unroll 8
        for (int j = 0; j < 64; j++) {
            float hj = v0 * Wr1[j] + v1 * Wr1[64 + j] + v2 * Wr1[128 + j] + br1[j];
            hj = fmaxf(hj, 0.f);
            o0 += hj * Wr2[j * 3 + 0];
            o1 += hj * Wr2[j * 3 + 1];
            o2 += hj * Wr2[j * 3 + 2];
        }
        out[g * 3 + 0] = o0;
        out[g * 3 + 1] = o1;
        out[g * 3 + 2] = o2;
    }
    __syncthreads();
    // restore invariants for next replay (pool read is complete)
    if (threadIdx.x < N_GRAPHS * 4) g_pool[threadIdx.x] = 0.f;
    if (threadIdx.x == 0) g_done = 0;
}

// ---------------- launch ----------------------------------------------------
extern "C" void kernel_launch(void* const* d_in, const int* in_sizes, int n_in,
                              void* d_out, int out_size) {
    (void)in_sizes; (void)n_in; (void)out_size;
    const float* x    = (const float*)d_in[0];
    const int*   ei   = (const int*)  d_in[1];
    const int*   batch= (const int*)  d_in[2];
    const float* W1l  = (const float*)d_in[3];
    const float* W1r  = (const float*)d_in[4];
    const float* att1 = (const float*)d_in[5];
    const float* b1   = (const float*)d_in[6];
    const float* W2l  = (const float*)d_in[7];
    const float* W2r  = (const float*)d_in[8];
    const float* att2 = (const float*)d_in[9];
    const float* b2   = (const float*)d_in[10];
    const float* Wr1  = (const float*)d_in[11];
    const float* br1  = (const float*)d_in[12];
    const float* Wr2  = (const float*)d_in[13];
    const float* br2  = (const float*)d_in[14];
    float* out = (float*)d_out;

    {
        dim3 grid((N_NODES + 127) / 128, 2);   // 391 x 2 = 782 blocks
        gemm1_count_kernel<<<grid, 256>>>(x, W1l, W1r, ei, batch);   // #1
    }
    scan_local_kernel<<<NB_SCAN, 256>>>();                           // #2
    scan_apply_kernel<<<NB_SCAN, 256>>>();                           // #3
    csr_fill_kernel<<<(ET + 255) / 256, 256>>>(ei);                  // #4
    fused_l1_kernel<<<148 * 3, 256>>>(att1, b1, W2l, W2r);           // #5
    fused_l2_mlp_kernel<<<L2_BLOCKS, 256>>>(att2, b2, batch,
                                            Wr1, br1, Wr2, br2, out); // #6
}

// round 15
// speedup vs baseline: 1.0606x; 1.0606x over previous
#include <cuda_runtime.h>

#define N_NODES 50000
#define N_EDGES 800000
#define ET (N_EDGES + N_NODES)   // self-loops appended
#define N_GRAPHS 64
#define FULL 0xffffffffu
#define NB_SCAN ((N_NODES + 255) / 256)   // 196
#define L2_BLOCKS (N_NODES / 16)          // 3125 blocks, 2 dst/warp * 8 warps

// ---------------- scratch (device globals; zero at module load) ------------
__device__ __align__(16) float g_xl1[N_NODES * 128];
__device__ __align__(16) float g_xr1[N_NODES * 128];
__device__ __align__(16) float g_xl2[N_NODES * 4];
__device__ __align__(16) float g_xr2[N_NODES * 4];
__device__ int g_cnt[N_NODES];          // invariant: zero at kernel_launch entry
__device__ int g_rowptr[N_NODES + 1];
__device__ int g_cursor[N_NODES];
__device__ int g_csr_src[ET];
__device__ int g_bsum[NB_SCAN];
__device__ float g_pool[N_GRAPHS * 4];  // invariant: zero at kernel_launch entry
__device__ int g_done;                  // invariant: zero at kernel_launch entry

__device__ __forceinline__ float lrelu(float v) { return v > 0.f ? v : 0.2f * v; }

// f32x2 packed FMA (sm_100+): d = a*b + d, elementwise on packed pairs
#define FMA2(d, a, b) asm("fma.rn.f32x2 %0, %1, %2, %0;" : "+l"(d) : "l"(a), "l"(b))
__device__ __forceinline__ unsigned long long pack2(float lo, float hi) {
    unsigned long long r;
    asm("mov.b64 %0, {%1, %2};" : "=l"(r) : "f"(lo), "f"(hi));
    return r;
}
__device__ __forceinline__ void unpack2(unsigned long long v, float& lo, float& hi) {
    asm("mov.b64 {%0, %1}, %2;" : "=f"(lo), "=f"(hi) : "l"(v));
}

// ---------------- CSR: count incoming edges per dst (+ per-graph node cnt) -
__global__ void csr_count_kernel(const int* __restrict__ ei,
                                 const int* __restrict__ batch) {
    int e = blockIdx.x * blockDim.x + threadIdx.x;
    if (e < ET) {
        int dst = (e < N_EDGES) ? ei[N_EDGES + e] : (e - N_EDGES);
        atomicAdd(&g_cnt[dst], 1);
    }
    if (e < N_NODES) atomicAdd(&g_pool[batch[e] * 4 + 3], 1.f);
}

// ---------------- scan phase 1: per-block exclusive scan --------------------
__global__ void scan_local_kernel() {
    __shared__ int sh[256];
    int t = threadIdx.x;
    int i = blockIdx.x * 256 + t;
    int v = (i < N_NODES) ? g_cnt[i] : 0;
    sh[t] = v;
    __syncthreads();
#pragma unroll
    for (int off = 1; off < 256; off <<= 1) {
        int u = (t >= off) ? sh[t - off] : 0;
        __syncthreads();
        sh[t] += u;
        __syncthreads();
    }
    if (i < N_NODES) g_rowptr[i] = sh[t] - v;          // exclusive within block
    if (t == 255) g_bsum[blockIdx.x] = sh[255];        // block total
}

// ---------------- scan phase 2: apply + restore g_cnt invariant -------------
__global__ void scan_apply_kernel() {
    __shared__ int sh[256];
    int t = threadIdx.x, bid = blockIdx.x;
    sh[t] = (t < bid) ? g_bsum[t] : 0;   // NB_SCAN = 196 <= 256
    __syncthreads();
#pragma unroll
    for (int off = 128; off; off >>= 1) {
        if (t < off) sh[t] += sh[t + off];
        __syncthreads();
    }
    int boff = sh[0];
    int i = bid * 256 + t;
    if (i < N_NODES) {
        int r = g_rowptr[i] + boff;
        g_rowptr[i] = r;
        g_cursor[i] = r;
        g_cnt[i] = 0;                    // g_cnt dead after this: restore invariant
    }
    if (i == 0) g_rowptr[N_NODES] = ET;
}

// ---------------- CSR: scatter src ids into slots --------------------------
__global__ void csr_fill_kernel(const int* __restrict__ ei) {
    int e = blockIdx.x * blockDim.x + threadIdx.x;
    if (e >= ET) return;
    int src, dst;
    if (e < N_EDGES) { src = ei[e]; dst = ei[N_EDGES + e]; }
    else             { src = dst = e - N_EDGES; }
    int pos = atomicAdd(&g_cursor[dst], 1);
    g_csr_src[pos] = src;
}

// ---------------- GEMM1 v3: 128x128 tile, K-chunked smem, reg-tiled --------
#define G3_KC 32
#define G3_PAD 132
__global__ void __launch_bounds__(256, 2)
gemm1_kernel(const float* __restrict__ x,
             const float* __restrict__ Wl,
             const float* __restrict__ Wr) {
    __shared__ float xs[G3_KC][G3_PAD];
    __shared__ float ws[G3_KC][G3_PAD];
    int row0 = blockIdx.x * 128;
    const float* W = blockIdx.y ? Wr : Wl;
    int tid = threadIdx.x;
    int rg = tid >> 3;
    int cg = tid & 7;

    unsigned long long acc[4][8];
#pragma unroll
    for (int r = 0; r < 4; r++)
#pragma unroll
        for (int c = 0; c < 8; c++) acc[r][c] = 0ull;

    for (int k0 = 0; k0 < 128; k0 += G3_KC) {
        {
            int r = tid >> 1;
            int kb = (tid & 1) * 16;
            int grow = row0 + r;
#pragma unroll
            for (int j4 = 0; j4 < 4; j4++) {
                float4 v = make_float4(0.f, 0.f, 0.f, 0.f);
                if (grow < N_NODES)
                    v = *(const float4*)(x + (size_t)grow * 128 + k0 + kb + j4 * 4);
                xs[kb + j4 * 4 + 0][r] = v.x;
                xs[kb + j4 * 4 + 1][r] = v.y;
                xs[kb + j4 * 4 + 2][r] = v.z;
                xs[kb + j4 * 4 + 3][r] = v.w;
            }
        }
        {
            int k = tid >> 3;
            int cs = (tid & 7) * 16;
#pragma unroll
            for (int j4 = 0; j4 < 4; j4++) {
                float4 v = *(const float4*)(W + (size_t)(k0 + k) * 128 + cs + j4 * 4);
                *(float4*)&ws[k][cs + j4 * 4] = v;
            }
        }
        __syncthreads();
#pragma unroll 4
        for (int k = 0; k < G3_KC; k++) {
            float4 av = *(const float4*)&xs[k][rg * 4];
            unsigned long long ap[4];
            ap[0] = pack2(av.x, av.x);
            ap[1] = pack2(av.y, av.y);
            ap[2] = pack2(av.z, av.z);
            ap[3] = pack2(av.w, av.w);
#pragma unroll
            for (int s = 0; s < 4; s++) {
                float4 bv = *(const float4*)&ws[k][cg * 4 + s * 32];
                unsigned long long b0 = pack2(bv.x, bv.y);
                unsigned long long b1 = pack2(bv.z, bv.w);
#pragma unroll
                for (int r = 0; r < 4; r++) {
                    FMA2(acc[r][2 * s + 0], ap[r], b0);
                    FMA2(acc[r][2 * s + 1], ap[r], b1);
                }
            }
        }
        __syncthreads();
    }

    float* outbuf = blockIdx.y ? g_xr1 : g_xl1;
#pragma unroll
    for (int r = 0; r < 4; r++) {
        int grow = row0 + rg * 4 + r;
        if (grow >= N_NODES) continue;
#pragma unroll
        for (int s = 0; s < 4; s++) {
            float4 o;
            unpack2(acc[r][2 * s + 0], o.x, o.y);
            unpack2(acc[r][2 * s + 1], o.z, o.w);
            *(float4*)(outbuf + (size_t)grow * 128 + cg * 4 + s * 32) = o;
        }
    }
}

// ---------------- fused layer1 + bias + ELU + GEMM2: warp per dst ----------
// lanes 0-15 head0 (ch 0..63), 16-31 head1. 4 edges in flight per warp
// (fits the 82-reg cap of launch_bounds(256,3) WITHOUT local-memory spills).
#define L1_UN 4
__global__ void __launch_bounds__(256, 3)
fused_l1_kernel(const float* __restrict__ att1,
                const float* __restrict__ b1,
                const float* __restrict__ W2l,
                const float* __restrict__ W2r) {
    int dst = (blockIdx.x * blockDim.x + threadIdx.x) >> 5;
    if (dst >= N_NODES) return;
    int lane = threadIdx.x & 31;
    int c0 = lane * 4;

    float4 b  = *(const float4*)(g_xr1 + (size_t)dst * 128 + c0);
    float4 at = *(const float4*)(att1 + c0);

    float4 acc = make_float4(0.f, 0.f, 0.f, 0.f);
    float denom = 0.f;

    int rs = g_rowptr[dst], re = g_rowptr[dst + 1];
    int i = rs;
    for (; i + L1_UN <= re; i += L1_UN) {
        int s[L1_UN];
#pragma unroll
        for (int u = 0; u < L1_UN; u++) s[u] = g_csr_src[i + u];   // uniform bcast
        float4 A[L1_UN];
#pragma unroll
        for (int u = 0; u < L1_UN; u++)
            A[u] = *(const float4*)(g_xl1 + (size_t)s[u] * 128 + c0);
        float P[L1_UN];
#pragma unroll
        for (int u = 0; u < L1_UN; u++)
            P[u] = at.x * lrelu(A[u].x + b.x) + at.y * lrelu(A[u].y + b.y)
                 + at.z * lrelu(A[u].z + b.z) + at.w * lrelu(A[u].w + b.w);
#pragma unroll
        for (int o = 8; o; o >>= 1) {   // 16-lane groups => per-head sums
#pragma unroll
            for (int u = 0; u < L1_UN; u++) P[u] += __shfl_xor_sync(FULL, P[u], o);
        }
#pragma unroll
        for (int u = 0; u < L1_UN; u++) {
            float e = __expf(P[u]);
            denom += e;
            acc.x += e * A[u].x; acc.y += e * A[u].y;
            acc.z += e * A[u].z; acc.w += e * A[u].w;
        }
    }
    for (; i < re; i++) {
        int src = g_csr_src[i];
        float4 a = *(const float4*)(g_xl1 + (size_t)src * 128 + c0);
        float p = at.x * lrelu(a.x + b.x) + at.y * lrelu(a.y + b.y)
                + at.z * lrelu(a.z + b.z) + at.w * lrelu(a.w + b.w);
#pragma unroll
        for (int o = 8; o; o >>= 1) p += __shfl_xor_sync(FULL, p, o);
        float ea = __expf(p);
        denom += ea;
        acc.x += ea * a.x; acc.y += ea * a.y;
        acc.z += ea * a.z; acc.w += ea * a.w;
    }

    float w = __fdividef(1.f, denom + 1e-16f);
    float4 bias = *(const float4*)(b1 + c0);
    float ov[4];
    ov[0] = acc.x * w + bias.x;
    ov[1] = acc.y * w + bias.y;
    ov[2] = acc.z * w + bias.z;
    ov[3] = acc.w * w + bias.w;
#pragma unroll
    for (int j = 0; j < 4; j++)
        ov[j] = ov[j] > 0.f ? ov[j] : (__expf(ov[j]) - 1.f);   // ELU

    float pl0 = 0.f, pl1 = 0.f, pl2 = 0.f, pr0 = 0.f, pr1 = 0.f, pr2 = 0.f;
#pragma unroll
    for (int j = 0; j < 4; j++) {
        int k = c0 + j;
        pl0 += ov[j] * W2l[k * 3 + 0];
        pl1 += ov[j] * W2l[k * 3 + 1];
        pl2 += ov[j] * W2l[k * 3 + 2];
        pr0 += ov[j] * W2r[k * 3 + 0];
        pr1 += ov[j] * W2r[k * 3 + 1];
        pr2 += ov[j] * W2r[k * 3 + 2];
    }
#pragma unroll
    for (int s = 16; s; s >>= 1) {
        pl0 += __shfl_xor_sync(FULL, pl0, s);
        pl1 += __shfl_xor_sync(FULL, pl1, s);
        pl2 += __shfl_xor_sync(FULL, pl2, s);
        pr0 += __shfl_xor_sync(FULL, pr0, s);
        pr1 += __shfl_xor_sync(FULL, pr1, s);
        pr2 += __shfl_xor_sync(FULL, pr2, s);
    }
    if (lane == 0) {
        *(float4*)(g_xl2 + dst * 4) = make_float4(pl0, pl1, pl2, 0.f);
        *(float4*)(g_xr2 + dst * 4) = make_float4(pr0, pr1, pr2, 0.f);
    }
}

// ---------------- fused layer2 + pool + (last block) MLP --------------------
// 2 dsts per warp: lanes 0-15 -> dst0, lanes 16-31 -> dst1.
__global__ void fused_l2_mlp_kernel(const float* __restrict__ att2,
                                    const float* __restrict__ b2,
                                    const int* __restrict__ batch,
                                    const float* __restrict__ Wr1,
                                    const float* __restrict__ br1,
                                    const float* __restrict__ Wr2,
                                    const float* __restrict__ br2,
                                    float* __restrict__ out) {
    int warp_g = (blockIdx.x * blockDim.x + threadIdx.x) >> 5;
    int lane = threadIdx.x & 31;
    int sl = lane & 15;
    int dst = warp_g * 2 + (lane >> 4);

    if (dst < N_NODES) {
        float a0 = att2[0], a1 = att2[1], a2 = att2[2];
        float4 rv = *(const float4*)(g_xr2 + dst * 4);
        float d = 0.f, m0 = 0.f, m1 = 0.f, m2 = 0.f;
        int rs = g_rowptr[dst], re = g_rowptr[dst + 1];
        for (int i = rs + sl; i < re; i += 16) {
            int src = g_csr_src[i];
            float4 sv = *(const float4*)(g_xl2 + src * 4);
            float p = a0 * lrelu(sv.x + rv.x) + a1 * lrelu(sv.y + rv.y)
                    + a2 * lrelu(sv.z + rv.z);
            float ea = __expf(p);
            d += ea; m0 += ea * sv.x; m1 += ea * sv.y; m2 += ea * sv.z;
        }
#pragma unroll
        for (int o = 8; o; o >>= 1) {   // reduce within 16-lane group
            d  += __shfl_xor_sync(FULL, d, o);
            m0 += __shfl_xor_sync(FULL, m0, o);
            m1 += __shfl_xor_sync(FULL, m1, o);
            m2 += __shfl_xor_sync(FULL, m2, o);
        }
        if (sl == 0) {
            float w = __fdividef(1.f, d + 1e-16f);
            int g = batch[dst];
            atomicAdd(&g_pool[g * 4 + 0], m0 * w + b2[0]);
            atomicAdd(&g_pool[g * 4 + 1], m1 * w + b2[1]);
            atomicAdd(&g_pool[g * 4 + 2], m2 * w + b2[2]);
        }
    }

    // ---- last-block ticket: the final block to finish runs the MLP ----
    __syncthreads();
    __shared__ int s_last;
    if (threadIdx.x == 0) {
        __threadfence();
        int ticket = atomicAdd(&g_done, 1);
        s_last = (ticket == gridDim.x - 1) ? 1 : 0;
    }
    __syncthreads();
    if (!s_last) return;
    __threadfence();   // acquire: all pool atomics now visible

    int g = threadIdx.x;
    if (g < N_GRAPHS) {
        float cnt = g_pool[g * 4 + 3];
        float inv = 1.f / fmaxf(cnt, 1.f);
        float v0 = g_pool[g * 4 + 0] * inv;
        float v1 = g_pool[g * 4 + 1] * inv;
        float v2 = g_pool[g * 4 + 2] * inv;
        float o0 = br2[0], o1 = br2[1], o2 = br2[2];
#pragma unroll 8
        for (int j = 0; j < 64; j++) {
            float hj = v0 * Wr1[j] + v1 * Wr1[64 + j] + v2 * Wr1[128 + j] + br1[j];
            hj = fmaxf(hj, 0.f);
            o0 += hj * Wr2[j * 3 + 0];
            o1 += hj * Wr2[j * 3 + 1];
            o2 += hj * Wr2[j * 3 + 2];
        }
        out[g * 3 + 0] = o0;
        out[g * 3 + 1] = o1;
        out[g * 3 + 2] = o2;
    }
    __syncthreads();
    // restore invariants for next replay (pool read is complete)
    if (threadIdx.x < N_GRAPHS * 4) g_pool[threadIdx.x] = 0.f;
    if (threadIdx.x == 0) g_done = 0;
}

// ---------------- stream/event handles (created at static init) -------------
struct SideStream {
    cudaStream_t s;
    cudaEvent_t evFork, evJoin;
    SideStream() {
        cudaStreamCreateWithFlags(&s, cudaStreamNonBlocking);
        cudaEventCreateWithFlags(&evFork, cudaEventDisableTiming);
        cudaEventCreateWithFlags(&evJoin, cudaEventDisableTiming);
    }
};
static SideStream g_ss;

// ---------------- launch ----------------------------------------------------
extern "C" void kernel_launch(void* const* d_in, const int* in_sizes, int n_in,
                              void* d_out, int out_size) {
    (void)in_sizes; (void)n_in; (void)out_size;
    const float* x    = (const float*)d_in[0];
    const int*   ei   = (const int*)  d_in[1];
    const int*   batch= (const int*)  d_in[2];
    const float* W1l  = (const float*)d_in[3];
    const float* W1r  = (const float*)d_in[4];
    const float* att1 = (const float*)d_in[5];
    const float* b1   = (const float*)d_in[6];
    const float* W2l  = (const float*)d_in[7];
    const float* W2r  = (const float*)d_in[8];
    const float* att2 = (const float*)d_in[9];
    const float* b2   = (const float*)d_in[10];
    const float* Wr1  = (const float*)d_in[11];
    const float* br1  = (const float*)d_in[12];
    const float* Wr2  = (const float*)d_in[13];
    const float* br2  = (const float*)d_in[14];
    float* out = (float*)d_out;

    // fork: gemm1 runs concurrently with the CSR build
    cudaEventRecord(g_ss.evFork, 0);
    cudaStreamWaitEvent(g_ss.s, g_ss.evFork, 0);
    {
        dim3 grid((N_NODES + 127) / 128, 2);
        gemm1_kernel<<<grid, 256, 0, g_ss.s>>>(x, W1l, W1r);
    }
    cudaEventRecord(g_ss.evJoin, g_ss.s);

    csr_count_kernel<<<(ET + 255) / 256, 256>>>(ei, batch);
    scan_local_kernel<<<NB_SCAN, 256>>>();
    scan_apply_kernel<<<NB_SCAN, 256>>>();
    csr_fill_kernel<<<(ET + 255) / 256, 256>>>(ei);

    // join: fused_l1 needs both gemm1 output and CSR
    cudaStreamWaitEvent(0, g_ss.evJoin, 0);
    {
        long long t = (long long)N_NODES * 32;
        fused_l1_kernel<<<(unsigned)((t + 255) / 256), 256>>>(att1, b1, W2l, W2r);
    }
    fused_l2_mlp_kernel<<<L2_BLOCKS, 256>>>(att2, b2, batch,
                                            Wr1, br1, Wr2, br2, out);
}